// round 3
// baseline (speedup 1.0000x reference)
#include <cuda_runtime.h>
#include <math.h>

#define PI_F      3.14159265358979323846f
#define TWO_PI_F  6.28318530717958647692f
#define N_NEUR    512
#define GW        (PI_F / 4.0f)

// Scratch (no allocations allowed in kernel_launch)
__device__ float g_bearing[N_NEUR];
__device__ float g_sum_hpc;

__device__ __forceinline__ float period_bound(float d) {
    // jnp.mod(d + pi, 2pi) - pi   (mod result in [0, 2pi))
    float m = fmodf(d + PI_F, TWO_PI_F);
    if (m < 0.0f) m += TWO_PI_F;
    return m - PI_F;
}

// ---------------------------------------------------------------------------
// Kernel A: zero the bearing accumulator, reduce sum(r_hpc).
// ---------------------------------------------------------------------------
__global__ void init_kernel(const float* __restrict__ r_hpc, int P) {
    __shared__ float s_red[N_NEUR];
    int tid = threadIdx.x;
    g_bearing[tid] = 0.0f;
    float s = 0.0f;
    for (int i = tid; i < P; i += N_NEUR) s += r_hpc[i];
    s_red[tid] = s;
    __syncthreads();
    #pragma unroll
    for (int off = 256; off > 0; off >>= 1) {
        if (tid < off) s_red[tid] += s_red[tid + off];
        __syncthreads();
    }
    if (tid == 0) g_sum_hpc = s_red[0];
}

// ---------------------------------------------------------------------------
// Kernel B: input_bearing_raw[n] = sum_p sum_l conn[p,n,l]*r_bearing[l]*r_hpc[p]
// One p-slab = 512*30 = 15360 floats = 7680 float2 = 512 threads x 15 float2.
// Thread t owns float2 flat indices {t + 512*j : j=0..14} -> every warp load is
// a contiguous 256B LDG.64 (fully coalesced). Accumulate over p in registers,
// demultiplex (n,l) + apply r_bearing + scatter ONCE per block at the end.
// ---------------------------------------------------------------------------
__global__ void __launch_bounds__(512, 2) bearing_kernel(
    const float2* __restrict__ conn,      // (P, 512, 30) viewed as float2
    const float*  __restrict__ r_hpc,     // (P,)
    const float*  __restrict__ r_bearing, // (30,)
    int P)
{
    __shared__ float s_rb[30];
    __shared__ float s_out[N_NEUR];
    const int tid = threadIdx.x;

    if (tid < 30) s_rb[tid] = r_bearing[tid];
    s_out[tid] = 0.0f;
    __syncthreads();

    float2 acc[15];
    #pragma unroll
    for (int j = 0; j < 15; j++) { acc[j].x = 0.0f; acc[j].y = 0.0f; }

    for (int p = blockIdx.x; p < P; p += gridDim.x) {
        const float w = __ldg(r_hpc + p);
        const float2* slab = conn + (size_t)p * 7680;
        #pragma unroll
        for (int j = 0; j < 15; j++) {
            float2 val = __ldg(slab + j * 512 + tid);
            acc[j].x = fmaf(w, val.x, acc[j].x);
            acc[j].y = fmaf(w, val.y, acc[j].y);
        }
    }

    // Demultiplex flat index -> (n, l), weight by r_bearing[l], scatter.
    #pragma unroll
    for (int j = 0; j < 15; j++) {
        int f0 = 2 * (j * 512 + tid);       // flat float index in slab
        int n0 = f0 / 30, l0 = f0 - n0 * 30;
        int f1 = f0 + 1;
        int n1 = f1 / 30, l1 = f1 - n1 * 30;
        atomicAdd(&s_out[n0], acc[j].x * s_rb[l0]);
        atomicAdd(&s_out[n1], acc[j].y * s_rb[l1]);
    }
    __syncthreads();
    atomicAdd(&g_bearing[tid], s_out[tid]);
}

// ---------------------------------------------------------------------------
// Kernel C: everything else (N=512, one block).
// ---------------------------------------------------------------------------
__global__ void final_kernel(
    const float* __restrict__ r,
    const float* __restrict__ u,
    const float* __restrict__ v,
    const float* __restrict__ pos_estimate,
    const float* __restrict__ angular_velocity,
    const float* __restrict__ sen2hd,
    const float* __restrict__ shared_t,
    float* __restrict__ out)
{
    __shared__ float s_r[N_NEUR];
    __shared__ float s_conn[N_NEUR];
    __shared__ float s_red[N_NEUR];

    const float DX   = TWO_PI_F / 512.0f;
    const float J0   = 20.0f / 512.0f;
    const float KPAR = 0.8f / 512.0f * 20.0f;
    const int n = threadIdx.x;

    const float xn = -PI_F + n * DX;
    const float rn = r[n];
    s_r[n] = rn;

    // conn[j] = J0 * exp(-0.5*(d_j/GW)^2) / (2*pi*GW^2), d_j = dist(|x0 - x_j|)
    {
        float dj = period_bound(n * DX);
        float q  = dj / GW;
        s_conn[n] = J0 * expf(-0.5f * q * q) / (TWO_PI_F * GW * GW);
    }

    // --- bump center: angle(sum exp(i x) r) ---
    s_red[n] = cosf(xn) * rn;
    __syncthreads();
    #pragma unroll
    for (int off = 256; off > 0; off >>= 1) {
        if (n < off) s_red[n] += s_red[n + off];
        __syncthreads();
    }
    const float csum = s_red[0];
    __syncthreads();
    s_red[n] = sinf(xn) * rn;
    __syncthreads();
    #pragma unroll
    for (int off = 256; off > 0; off >>= 1) {
        if (n < off) s_red[n] += s_red[n + off];
        __syncthreads();
    }
    const float ssum = s_red[0];
    __syncthreads();
    const float center = atan2f(ssum, csum);

    // --- path integration (DT = 0.1 is the config constant) ---
    float pos = pos_estimate[0];
    float pe  = pos + (period_bound(center - pos) / 1000.0f + angular_velocity[0]) * 0.1f;
    pos = period_bound(pe);

    // motion input
    float dd = period_bound(xn - pos) / GW;
    const float motion = 3.0f * expf(-0.25f * dd * dd);

    // --- recurrent input: circular convolution Irec[n] = sum_m conn[m]*r[(n-m) mod N]
    float irec = 0.0f;
    #pragma unroll 8
    for (int m = 0; m < N_NEUR; m++)
        irec = fmaf(s_conn[m], s_r[(n - m) & (N_NEUR - 1)], irec);

    // --- bearing input (normalized) ---
    const float ib = g_bearing[n] / g_sum_hpc;

    const float input_total = motion + irec + ib * sen2hd[0];

    // --- exact exponential ODE step for u (v1 never feeds the output) ---
    const float dt_ode = shared_t[1] - shared_t[0];
    const float C1 = input_total - v[n];
    const float u1 = C1 + (u[n] - C1) * expf(-dt_ode /* / TAU=1 */);

    const float un = u1 > 0.0f ? u1 : 0.0f;
    const float r1 = un * un;

    s_red[n] = r1;
    __syncthreads();
    #pragma unroll
    for (int off = 256; off > 0; off >>= 1) {
        if (n < off) s_red[n] += s_red[n + off];
        __syncthreads();
    }
    const float sum_r1 = s_red[0];

    out[n] = r1 / (1.0f + KPAR * sum_r1);
}

// ---------------------------------------------------------------------------
// Launch
// ---------------------------------------------------------------------------
extern "C" void kernel_launch(void* const* d_in, const int* in_sizes, int n_in,
                              void* d_out, int out_size) {
    const float* conn      = (const float*)d_in[0];   // (P, 512, 30)
    const float* r         = (const float*)d_in[1];   // (512,)
    const float* u         = (const float*)d_in[2];   // (512,)
    const float* v         = (const float*)d_in[3];   // (512,)
    const float* r_hpc     = (const float*)d_in[4];   // (P,)
    const float* r_bearing = (const float*)d_in[5];   // (30,)
    const float* pos_est   = (const float*)d_in[6];   // (1,)
    const float* ang_vel   = (const float*)d_in[7];   // (1,)
    // d_in[8] = HD, unused (get_HD = 0 path)
    const float* sen2hd    = (const float*)d_in[9];   // (1,)
    const float* shared_t  = (const float*)d_in[10];  // (2,)
    float* out = (float*)d_out;

    const int P = in_sizes[4];  // r_hpc length

    init_kernel<<<1, N_NEUR>>>(r_hpc, P);
    bearing_kernel<<<296, N_NEUR>>>((const float2*)conn, r_hpc, r_bearing, P);
    final_kernel<<<1, N_NEUR>>>(r, u, v, pos_est, ang_vel, sen2hd, shared_t, out);
}

// round 4
// speedup vs baseline: 1.0621x; 1.0621x over previous
#include <cuda_runtime.h>
#include <math.h>

#define PI_F      3.14159265358979323846f
#define TWO_PI_F  6.28318530717958647692f
#define N_NEUR    512
#define GW        (PI_F / 4.0f)

// Scratch (no allocations allowed in kernel_launch)
__device__ float g_bearing[N_NEUR];
__device__ float g_sum_hpc;

__device__ __forceinline__ float period_bound(float d) {
    // jnp.mod(d + pi, 2pi) - pi   (mod result in [0, 2pi))
    float m = fmodf(d + PI_F, TWO_PI_F);
    if (m < 0.0f) m += TWO_PI_F;
    return m - PI_F;
}

// ---------------------------------------------------------------------------
// Kernel A: zero the accumulators only (~1.5us). sum(r_hpc) is folded into
// the bearing kernel (each p is visited by exactly one block).
// ---------------------------------------------------------------------------
__global__ void zero_kernel() {
    int t = threadIdx.x;
    g_bearing[t] = 0.0f;
    if (t == 0) g_sum_hpc = 0.0f;
}

// ---------------------------------------------------------------------------
// Kernel B: input_bearing_raw[n] = sum_p sum_l conn[p,n,l]*r_bearing[l]*r_hpc[p]
// One p-slab = 512*30 = 15360 floats = 3840 float4 = 256 threads x 15 float4.
// Thread t owns float4 flat indices {t + 256*j : j=0..14} -> every warp load is
// a fully-coalesced 512B LDG.128. launch_bounds(256,2) gives 128 regs/thread:
// 60 accumulator regs + headroom for ptxas to pipeline loads across the
// p-iteration boundary. __ldcs: 614MB is read exactly once, skip L2 retention.
// Demultiplex (n,l) + apply r_bearing + scatter ONCE per block at the end.
// ---------------------------------------------------------------------------
__global__ void __launch_bounds__(256, 2) bearing_kernel(
    const float4* __restrict__ conn,      // (P, 512, 30) viewed as float4
    const float*  __restrict__ r_hpc,     // (P,)
    const float*  __restrict__ r_bearing, // (30,)
    int P)
{
    __shared__ float s_rb[30];
    __shared__ float s_out[N_NEUR];
    const int tid = threadIdx.x;

    if (tid < 30) s_rb[tid] = r_bearing[tid];
    s_out[tid] = 0.0f;
    s_out[tid + 256] = 0.0f;
    __syncthreads();

    float4 acc[15];
    #pragma unroll
    for (int j = 0; j < 15; j++) {
        acc[j].x = 0.0f; acc[j].y = 0.0f; acc[j].z = 0.0f; acc[j].w = 0.0f;
    }

    float wsum = 0.0f;
    for (int p = blockIdx.x; p < P; p += gridDim.x) {
        const float w = __ldg(r_hpc + p);
        wsum += w;
        const float4* slab = conn + (size_t)p * 3840;
        #pragma unroll
        for (int j = 0; j < 15; j++) {
            float4 val = __ldcs(slab + j * 256 + tid);
            acc[j].x = fmaf(w, val.x, acc[j].x);
            acc[j].y = fmaf(w, val.y, acc[j].y);
            acc[j].z = fmaf(w, val.z, acc[j].z);
            acc[j].w = fmaf(w, val.w, acc[j].w);
        }
    }

    // Demultiplex flat float index -> (n, l), weight by r_bearing[l], scatter.
    #pragma unroll
    for (int j = 0; j < 15; j++) {
        const int f = 4 * (j * 256 + tid);   // flat float index in slab
        float comp[4] = {acc[j].x, acc[j].y, acc[j].z, acc[j].w};
        #pragma unroll
        for (int c = 0; c < 4; c++) {
            int idx = f + c;
            int n = idx / 30;
            int l = idx - n * 30;
            atomicAdd(&s_out[n], comp[c] * s_rb[l]);
        }
    }
    __syncthreads();
    atomicAdd(&g_bearing[tid],       s_out[tid]);
    atomicAdd(&g_bearing[tid + 256], s_out[tid + 256]);
    // Each p visited exactly once globally -> partial sums add to sum(r_hpc).
    // All threads in the block computed the same wsum; only tid 0 contributes.
    if (tid == 0) atomicAdd(&g_sum_hpc, wsum);
}

// ---------------------------------------------------------------------------
// Kernel C: everything else (N=512, one block).
// ---------------------------------------------------------------------------
__global__ void final_kernel(
    const float* __restrict__ r,
    const float* __restrict__ u,
    const float* __restrict__ v,
    const float* __restrict__ pos_estimate,
    const float* __restrict__ angular_velocity,
    const float* __restrict__ sen2hd,
    const float* __restrict__ shared_t,
    float* __restrict__ out)
{
    __shared__ float s_r[N_NEUR];
    __shared__ float s_conn[N_NEUR];
    __shared__ float s_red[N_NEUR];

    const float DX   = TWO_PI_F / 512.0f;
    const float J0   = 20.0f / 512.0f;
    const float KPAR = 0.8f / 512.0f * 20.0f;
    const int n = threadIdx.x;

    const float xn = -PI_F + n * DX;
    const float rn = r[n];
    s_r[n] = rn;

    // conn[j] = J0 * exp(-0.5*(d_j/GW)^2) / (2*pi*GW^2), d_j = dist(|x0 - x_j|)
    {
        float dj = period_bound(n * DX);
        float q  = dj / GW;
        s_conn[n] = J0 * expf(-0.5f * q * q) / (TWO_PI_F * GW * GW);
    }

    // --- bump center: angle(sum exp(i x) r) ---
    s_red[n] = cosf(xn) * rn;
    __syncthreads();
    #pragma unroll
    for (int off = 256; off > 0; off >>= 1) {
        if (n < off) s_red[n] += s_red[n + off];
        __syncthreads();
    }
    const float csum = s_red[0];
    __syncthreads();
    s_red[n] = sinf(xn) * rn;
    __syncthreads();
    #pragma unroll
    for (int off = 256; off > 0; off >>= 1) {
        if (n < off) s_red[n] += s_red[n + off];
        __syncthreads();
    }
    const float ssum = s_red[0];
    __syncthreads();
    const float center = atan2f(ssum, csum);

    // --- path integration (DT = 0.1 is the config constant) ---
    float pos = pos_estimate[0];
    float pe  = pos + (period_bound(center - pos) / 1000.0f + angular_velocity[0]) * 0.1f;
    pos = period_bound(pe);

    // motion input
    float dd = period_bound(xn - pos) / GW;
    const float motion = 3.0f * expf(-0.25f * dd * dd);

    // --- recurrent input: circular convolution Irec[n] = sum_m conn[m]*r[(n-m) mod N]
    float irec = 0.0f;
    #pragma unroll 8
    for (int m = 0; m < N_NEUR; m++)
        irec = fmaf(s_conn[m], s_r[(n - m) & (N_NEUR - 1)], irec);

    // --- bearing input (normalized) ---
    const float ib = g_bearing[n] / g_sum_hpc;

    const float input_total = motion + irec + ib * sen2hd[0];

    // --- exact exponential ODE step for u (v1 never feeds the output) ---
    const float dt_ode = shared_t[1] - shared_t[0];
    const float C1 = input_total - v[n];
    const float u1 = C1 + (u[n] - C1) * expf(-dt_ode /* / TAU=1 */);

    const float un = u1 > 0.0f ? u1 : 0.0f;
    const float r1 = un * un;

    s_red[n] = r1;
    __syncthreads();
    #pragma unroll
    for (int off = 256; off > 0; off >>= 1) {
        if (n < off) s_red[n] += s_red[n + off];
        __syncthreads();
    }
    const float sum_r1 = s_red[0];

    out[n] = r1 / (1.0f + KPAR * sum_r1);
}

// ---------------------------------------------------------------------------
// Launch
// ---------------------------------------------------------------------------
extern "C" void kernel_launch(void* const* d_in, const int* in_sizes, int n_in,
                              void* d_out, int out_size) {
    const float* conn      = (const float*)d_in[0];   // (P, 512, 30)
    const float* r         = (const float*)d_in[1];   // (512,)
    const float* u         = (const float*)d_in[2];   // (512,)
    const float* v         = (const float*)d_in[3];   // (512,)
    const float* r_hpc     = (const float*)d_in[4];   // (P,)
    const float* r_bearing = (const float*)d_in[5];   // (30,)
    const float* pos_est   = (const float*)d_in[6];   // (1,)
    const float* ang_vel   = (const float*)d_in[7];   // (1,)
    // d_in[8] = HD, unused (get_HD = 0 path)
    const float* sen2hd    = (const float*)d_in[9];   // (1,)
    const float* shared_t  = (const float*)d_in[10];  // (2,)
    float* out = (float*)d_out;

    const int P = in_sizes[4];  // r_hpc length

    zero_kernel<<<1, N_NEUR>>>();
    bearing_kernel<<<296, 256>>>((const float4*)conn, r_hpc, r_bearing, P);
    final_kernel<<<1, N_NEUR>>>(r, u, v, pos_est, ang_vel, sen2hd, shared_t, out);
}

// round 5
// speedup vs baseline: 1.2219x; 1.1505x over previous
#include <cuda_runtime.h>
#include <math.h>
#include <stdint.h>

#define PI_F      3.14159265358979323846f
#define TWO_PI_F  6.28318530717958647692f
#define N_NEUR    512
#define GW        (PI_F / 4.0f)
#define GRID      148
#define DEPTH     3
#define NL        30
#define SLAB_FLOATS (N_NEUR * NL)          // 15360 floats
#define SLAB_BYTES  (SLAB_FLOATS * 4)      // 61440 bytes

// Scratch (static device memory; no allocations anywhere)
__device__ float g_partial[GRID * N_NEUR];
__device__ int   g_count = 0;

__device__ __forceinline__ float period_bound(float d) {
    // jnp.mod(d + pi, 2pi) - pi   (mod result in [0, 2pi))
    float m = fmodf(d + PI_F, TWO_PI_F);
    if (m < 0.0f) m += TWO_PI_F;
    return m - PI_F;
}

__device__ __forceinline__ uint32_t smem_u32(const void* p) {
    return (uint32_t)__cvta_generic_to_shared(p);
}

__device__ __forceinline__ void mbar_init(uint32_t mb, uint32_t count) {
    asm volatile("mbarrier.init.shared.b64 [%0], %1;" :: "r"(mb), "r"(count) : "memory");
}

__device__ __forceinline__ void bulk_load(uint32_t dst_smem, const void* src_gmem,
                                          uint32_t bytes, uint32_t mb) {
    // expect_tx (1 arrival, count=1) then the bulk copy completing drains tx
    asm volatile("mbarrier.arrive.expect_tx.shared.b64 _, [%0], %1;"
                 :: "r"(mb), "r"(bytes) : "memory");
    asm volatile("cp.async.bulk.shared::cluster.global.mbarrier::complete_tx::bytes "
                 "[%0], [%1], %2, [%3];"
                 :: "r"(dst_smem), "l"(src_gmem), "r"(bytes), "r"(mb) : "memory");
}

__device__ __forceinline__ void mbar_wait(uint32_t mb, uint32_t parity) {
    asm volatile(
        "{\n\t"
        ".reg .pred p;\n\t"
        "WL_%=:\n\t"
        "mbarrier.try_wait.parity.shared.b64 p, [%0], %1;\n\t"
        "@!p bra WL_%=;\n\t"
        "}"
        :: "r"(mb), "r"(parity) : "memory");
}

// ---------------------------------------------------------------------------
// Single fused persistent kernel.
//  Phase 1 (all 148 blocks): stream conn slabs via cp.async.bulk 3-deep ring,
//    thread n accumulates acc = sum_p w_p * dot(conn[p,n,:], rb)  (1 register).
//  Phase 2 (last block only): reduce partials, sum(r_hpc), bump center,
//    path integration, circular conv, ODE, divisive normalization.
// ---------------------------------------------------------------------------
__global__ void __launch_bounds__(N_NEUR, 1) fused_kernel(
    const float* __restrict__ conn,      // (P, 512, 30)
    const float* __restrict__ r,
    const float* __restrict__ u,
    const float* __restrict__ v,
    const float* __restrict__ r_hpc,     // (P,)
    const float* __restrict__ r_bearing, // (30,)
    const float* __restrict__ pos_estimate,
    const float* __restrict__ angular_velocity,
    const float* __restrict__ sen2hd,
    const float* __restrict__ shared_t,
    float* __restrict__ out,
    int P)
{
    extern __shared__ float buf[];                 // DEPTH * SLAB_FLOATS
    __shared__ __align__(8) unsigned long long mbar[DEPTH];
    __shared__ int   s_last;
    __shared__ float s_red[N_NEUR];
    __shared__ float s_rr[N_NEUR];
    __shared__ float s_cn[N_NEUR];

    const int tid = threadIdx.x;
    const int bid = blockIdx.x;

    // rb into registers (uniform across threads; indices compile-time constant)
    float rbv[NL];
    #pragma unroll
    for (int l = 0; l < NL; l++) rbv[l] = __ldg(r_bearing + l);

    if (tid == 0) {
        #pragma unroll
        for (int s = 0; s < DEPTH; s++) mbar_init(smem_u32(&mbar[s]), 1u);
    }
    __syncthreads();

    // contiguous partition of p-range
    const int begin = (int)(((long long)bid * P) / GRID);
    const int end   = (int)(((long long)(bid + 1) * P) / GRID);
    const int M     = end - begin;

    if (tid == 0) {
        const int npro = M < DEPTH ? M : DEPTH;
        for (int s = 0; s < npro; s++) {
            bulk_load(smem_u32(buf + s * SLAB_FLOATS),
                      conn + (size_t)(begin + s) * SLAB_FLOATS,
                      SLAB_BYTES, smem_u32(&mbar[s]));
        }
    }

    float acc = 0.0f;
    for (int i = 0; i < M; i++) {
        const int s  = i % DEPTH;
        const int ph = (i / DEPTH) & 1;
        const float w = __ldg(r_hpc + begin + i);   // independent of barrier
        mbar_wait(smem_u32(&mbar[s]), (uint32_t)ph);

        const float* row = buf + s * SLAB_FLOATS + tid * NL;
        float dot = 0.0f;
        #pragma unroll
        for (int l = 0; l < NL; l++) dot = fmaf(row[l], rbv[l], dot);
        acc = fmaf(w, dot, acc);

        __syncthreads();                            // everyone done with buf[s]
        if (tid == 0 && i + DEPTH < M) {
            bulk_load(smem_u32(buf + s * SLAB_FLOATS),
                      conn + (size_t)(begin + i + DEPTH) * SLAB_FLOATS,
                      SLAB_BYTES, smem_u32(&mbar[s]));
        }
    }

    // publish partial (threadFenceReduction pattern)
    g_partial[bid * N_NEUR + tid] = acc;
    __threadfence();
    __syncthreads();
    if (tid == 0) {
        int old = atomicAdd(&g_count, 1);
        s_last = (old == GRID - 1);
    }
    __syncthreads();
    if (!s_last) return;

    // ------------------- last block: finish everything -------------------
    __threadfence();  // acquire all blocks' partials

    const int n = tid;

    // bearing reduction across blocks (coalesced, mostly L2 hits)
    float bear;
    {
        float b0 = 0.f, b1 = 0.f, b2 = 0.f, b3 = 0.f;
        #pragma unroll
        for (int b = 0; b < GRID; b += 4) {
            b0 += g_partial[(b + 0) * N_NEUR + n];
            b1 += g_partial[(b + 1) * N_NEUR + n];
            b2 += g_partial[(b + 2) * N_NEUR + n];
            b3 += g_partial[(b + 3) * N_NEUR + n];
        }
        bear = (b0 + b1) + (b2 + b3);
    }

    // sum(r_hpc)
    float sh = 0.0f;
    for (int i = n; i < P; i += N_NEUR) sh += __ldg(r_hpc + i);
    s_red[n] = sh;
    __syncthreads();
    #pragma unroll
    for (int off = 256; off > 0; off >>= 1) {
        if (n < off) s_red[n] += s_red[n + off];
        __syncthreads();
    }
    const float sum_hpc = s_red[0];
    __syncthreads();

    const float DX   = TWO_PI_F / 512.0f;
    const float J0   = 20.0f / 512.0f;
    const float KPAR = 0.8f / 512.0f * 20.0f;

    const float xn = -PI_F + n * DX;
    const float rn = r[n];
    s_rr[n] = rn;
    {
        float dj = period_bound(n * DX);
        float q  = dj / GW;
        s_cn[n] = J0 * expf(-0.5f * q * q) / (TWO_PI_F * GW * GW);
    }

    // bump center: angle(sum exp(i x) r)
    s_red[n] = cosf(xn) * rn;
    __syncthreads();
    #pragma unroll
    for (int off = 256; off > 0; off >>= 1) {
        if (n < off) s_red[n] += s_red[n + off];
        __syncthreads();
    }
    const float csum = s_red[0];
    __syncthreads();
    s_red[n] = sinf(xn) * rn;
    __syncthreads();
    #pragma unroll
    for (int off = 256; off > 0; off >>= 1) {
        if (n < off) s_red[n] += s_red[n + off];
        __syncthreads();
    }
    const float ssum = s_red[0];
    __syncthreads();
    const float center = atan2f(ssum, csum);

    // path integration (DT = 0.1 config constant, TAU_E = 1000)
    float pos = pos_estimate[0];
    float pe  = pos + (period_bound(center - pos) / 1000.0f + angular_velocity[0]) * 0.1f;
    pos = period_bound(pe);

    float dd = period_bound(xn - pos) / GW;
    const float motion = 3.0f * expf(-0.25f * dd * dd);

    // recurrent input: circular convolution
    float irec = 0.0f;
    #pragma unroll 8
    for (int m = 0; m < N_NEUR; m++)
        irec = fmaf(s_cn[m], s_rr[(n - m) & (N_NEUR - 1)], irec);

    const float ib = bear / sum_hpc;
    const float input_total = motion + irec + ib * sen2hd[0];

    // exact exponential ODE step for u (v1 never feeds the output)
    const float dt_ode = shared_t[1] - shared_t[0];
    const float C1 = input_total - v[n];
    const float u1 = C1 + (u[n] - C1) * expf(-dt_ode /* / TAU=1 */);

    const float un = u1 > 0.0f ? u1 : 0.0f;
    const float r1 = un * un;

    s_red[n] = r1;
    __syncthreads();
    #pragma unroll
    for (int off = 256; off > 0; off >>= 1) {
        if (n < off) s_red[n] += s_red[n + off];
        __syncthreads();
    }
    const float sum_r1 = s_red[0];

    out[n] = r1 / (1.0f + KPAR * sum_r1);

    if (n == 0) g_count = 0;   // reset for next graph replay
}

// ---------------------------------------------------------------------------
// Launch
// ---------------------------------------------------------------------------
extern "C" void kernel_launch(void* const* d_in, const int* in_sizes, int n_in,
                              void* d_out, int out_size) {
    const float* conn      = (const float*)d_in[0];   // (P, 512, 30)
    const float* r         = (const float*)d_in[1];   // (512,)
    const float* u         = (const float*)d_in[2];   // (512,)
    const float* v         = (const float*)d_in[3];   // (512,)
    const float* r_hpc     = (const float*)d_in[4];   // (P,)
    const float* r_bearing = (const float*)d_in[5];   // (30,)
    const float* pos_est   = (const float*)d_in[6];   // (1,)
    const float* ang_vel   = (const float*)d_in[7];   // (1,)
    // d_in[8] = HD, unused (get_HD = 0 path)
    const float* sen2hd    = (const float*)d_in[9];   // (1,)
    const float* shared_t  = (const float*)d_in[10];  // (2,)
    float* out = (float*)d_out;

    const int P = in_sizes[4];  // r_hpc length

    const int smem_bytes = DEPTH * SLAB_BYTES;  // 184320
    cudaFuncSetAttribute(fused_kernel,
                         cudaFuncAttributeMaxDynamicSharedMemorySize, smem_bytes);

    fused_kernel<<<GRID, N_NEUR, smem_bytes>>>(
        conn, r, u, v, r_hpc, r_bearing, pos_est, ang_vel, sen2hd, shared_t,
        out, P);
}